// round 15
// baseline (speedup 1.0000x reference)
#include <cuda_runtime.h>
#include <cstdint>

// ---------------------------------------------------------------------------
// SpikingNet, JAX threefry PARTITIONABLE mode (confirmed R4).
// R13 = R12 split into 2 CTAs/SM for independent barrier domains:
//   256 CTAs x 352 thr, 16 batch rows per CTA, __launch_bounds__(352, 2).
//   warps 0-3   (128 thr): GEMM 16x128x56 per chunk, ONE GEMM warp per SMSP
//                per CTA (2/SMSP per SM), per-thread 2 rows x 8 cols (FFMA2),
//                W staging (cp.async post-sync, race-free), LIF-1, layer2.
//   warps 4-10  (224 thr): threefry RNG -> gated xi; lane->row stores
//                (conflict-free STS.64); x in thread-local.
// 2-deep xi ring, named barriers FULL[b]=1+b, EMPTY[b]=3+b, GEMM=5.
// Per-output arithmetic identical to R4-R12 (ascending-k FMA chains).
// ---------------------------------------------------------------------------

namespace {
constexpr int F     = 784;
constexpr int KC    = 56;                 // K-chunk
constexpr int NCH   = 14;                 // 784/56
constexpr int H1    = 100;
constexpr int H2    = 10;
constexpr int ROWS  = 16;                 // batch rows per CTA
constexpr int WROW  = 140;                // swizzled W row pitch (words)
constexpr int WBUFW = KC * WROW;          // 7840 floats per W buffer
constexpr int AROW  = 18;                 // xit row pitch (float2)
constexpr int ABUF2 = KC * AROW;          // 1008 float2 per xi stage
constexpr int NSTEP = 98;                 // layer1 steps
constexpr int NG    = NSTEP * NCH;        // 1372 chunks
constexpr int TPB   = 352;

struct Smem {
  float    W[2 * WBUFW];          //  62,720 B (swizzled, dbl buffer)
  float2   xit[2 * ABUF2];        //  16,128 B ({v,v} dup, [stage][k][row])
  float    outer[ROWS][H1];       //   6,400 B
  float    inner1[ROWS][H1];      //   6,400 B
  float    W2s[H1][H2];           //   4,000 B
  float    b1s[H1];
  float    b2s[H2];
  float    outb[ROWS][H2];
  unsigned key0[NSTEP], key1[NSTEP];
};                                 // ~97.5 KB -> 2 CTAs/SM fits 227 KB

// W col-group swizzle (R6-proven, injective): group g (8 cols) at word
// (g/4)*36 + (g%4)*8, pitch 140.
__device__ __forceinline__ int woff(int g) { return (g >> 2) * 36 + (g & 3) * 8; }

__device__ __forceinline__ void tf2x32(unsigned k0, unsigned k1,
                                       unsigned x0, unsigned x1,
                                       unsigned& y0, unsigned& y1) {
  unsigned k2 = k0 ^ k1 ^ 0x1BD11BDAu;
#define TFR(r) { x0 += x1; x1 = __funnelshift_l(x1, x1, (r)); x1 ^= x0; }
  x0 += k0; x1 += k1;
  TFR(13) TFR(15) TFR(26) TFR(6)
  x0 += k1; x1 += k2 + 1u;
  TFR(17) TFR(29) TFR(16) TFR(24)
  x0 += k2; x1 += k0 + 2u;
  TFR(13) TFR(15) TFR(26) TFR(6)
  x0 += k0; x1 += k1 + 3u;
  TFR(17) TFR(29) TFR(16) TFR(24)
  x0 += k1; x1 += k2 + 4u;
  TFR(13) TFR(15) TFR(26) TFR(6)
  x0 += k2; x1 += k0 + 5u;
#undef TFR
  y0 = x0; y1 = x1;
}

__device__ __forceinline__ float u01(unsigned bits) {
  return __fadd_rn(__uint_as_float((bits >> 9) | 0x3F800000u), -1.0f);
}

__device__ __forceinline__ void ffma2(unsigned long long& d,
                                      unsigned long long a,
                                      unsigned long long b) {
  asm("fma.rn.f32x2 %0, %1, %2, %0;" : "+l"(d) : "l"(a), "l"(b));
}

__device__ __forceinline__ void lds2u64(unsigned long long& a,
                                        unsigned long long& b, unsigned addr) {
  asm volatile("ld.shared.v2.u64 {%0,%1}, [%2];" : "=l"(a), "=l"(b) : "r"(addr));
}

__device__ __forceinline__ void unpack2(unsigned long long v, float& lo, float& hi) {
  asm("mov.b64 {%0,%1}, %2;" : "=f"(lo), "=f"(hi) : "l"(v));
}

// FULL[b] = 1+b, EMPTY[b] = 3+b (b=0,1), GEMM-internal = 5 (per-CTA barriers)
#define BAR_SYNC_ALL(id)   asm volatile("bar.sync %0, 352;"   :: "r"(id) : "memory")
#define BAR_ARRIVE_ALL(id) asm volatile("bar.arrive %0, 352;" :: "r"(id) : "memory")
#define BAR_GEMM()         asm volatile("bar.sync 5, 128;" ::: "memory")

// stage W chunk (swizzled) via cp.async; GEMM threads only (stride 128)
__device__ __forceinline__ void stage_w(const float* __restrict__ gW1,
                                        Smem& sm, int chunk, int buf, int tid) {
  const float* src0 = gW1 + chunk * KC * H1;
  float* dst0 = &sm.W[buf * WBUFW];
  for (int seg = tid; seg < KC * 25; seg += 128) {
    int row = seg / 25, p = seg - row * 25;       // p: 16B piece (4 cols)
    int dw = row * WROW + woff(p >> 1) + (p & 1) * 4;
    unsigned d = (unsigned)__cvta_generic_to_shared(dst0 + dw);
    const float* s = src0 + row * H1 + p * 4;
    asm volatile("cp.async.ca.shared.global [%0], [%1], 16;\n" :: "r"(d), "l"(s));
  }
}
}  // namespace

__global__ void __launch_bounds__(TPB, 2)
snn_kernel(const float* __restrict__ gx, const float* __restrict__ gW1,
           const float* __restrict__ gb1, const float* __restrict__ gW2,
           const float* __restrict__ gb2, float* __restrict__ gout) {
  extern __shared__ char smraw[];
  Smem& sm = *reinterpret_cast<Smem*>(smraw);
  const int tid = threadIdx.x;
  const int rA0 = blockIdx.x * ROWS;

  // ---- init --------------------------------------------------------------
  for (int e = tid; e < 2 * WBUFW; e += TPB) sm.W[e] = 0.f;   // pad cols stay 0
  for (int e = tid; e < ROWS * H1; e += TPB) {
    (&sm.outer[0][0])[e]  = 0.f;
    (&sm.inner1[0][0])[e] = 0.f;
  }
  for (int e = tid; e < H1 * H2; e += TPB) (&sm.W2s[0][0])[e] = gW2[e];
  if (tid < H1) sm.b1s[tid] = gb1[tid];
  if (tid < H2) sm.b2s[tid] = gb2[tid];
  if (tid < NSTEP) {   // foldlike split: keys[t] = threefry((0,42),(0,t))
    unsigned a0, a1;
    tf2x32(0u, 42u, 0u, (unsigned)tid, a0, a1);
    sm.key0[tid] = a0; sm.key1[tid] = a1;
  }
  __syncthreads();

  if (tid < 128) {
    // =================== GEMM / layer2 half (warps 0-3) ===================
    const int tx = tid & 15;           // col group: cols tx*8 .. tx*8+7
    const int rg = tid >> 4;           // row pair: rows 2rg, 2rg+1 (rg 0..7)
    const unsigned wb0 = (unsigned)__cvta_generic_to_shared(&sm.W[0]) +
                         (unsigned)(woff(tx) * 4);
    const unsigned ab0 = (unsigned)__cvta_generic_to_shared(&sm.xit[0]) +
                         (unsigned)(rg * 16);        // rows 2rg: byte 16*rg
    // layer2 outputs: o = tid + 128*s (s<2), valid o<160; r=o/10, j=o%10
    float i2[2] = {0.f, 0.f}, a2[2] = {0.f, 0.f};

    stage_w(gW1, sm, 0, 0, tid);                 // prologue: chunk 0 -> buf 0
    asm volatile("cp.async.commit_group;\n");

    unsigned long long acc[2][4];
    int t = 0, c = 0;
    for (int g = 0; g < NG; ++g) {
      if (c == 0) {
        #pragma unroll
        for (int r = 0; r < 2; ++r)
          #pragma unroll
          for (int p = 0; p < 4; ++p) acc[r][p] = 0ull;
      }
      BAR_SYNC_ALL(1 + (g & 1));                 // xi stage g&1 full; all GEMM
                                                 // peers past chunk g-1 FFMA
      int nc = (c + 1 == NCH) ? 0 : c + 1;       // stage W AFTER rendezvous
      stage_w(gW1, sm, nc, (g + 1) & 1, tid);    // (race-free, R12-proven)
      asm volatile("cp.async.commit_group;\n");
      asm volatile("cp.async.wait_group 1;\n");  // W[g&1] ready

      const unsigned wB = wb0 + (unsigned)((g & 1) * (WBUFW * 4));
      const unsigned aB = ab0 + (unsigned)((g & 1) * (ABUF2 * 8));
      #pragma unroll 8
      for (int k = 0; k < KC; ++k) {
        unsigned long long a0, a1, w01, w23, w45, w67;
        lds2u64(a0, a1,   aB + (unsigned)k * 144u);        // rows 2rg,2rg+1
        lds2u64(w01, w23, wB + (unsigned)k * 560u);        // cols tx*8..+3
        lds2u64(w45, w67, wB + (unsigned)k * 560u + 16u);  // cols tx*8+4..+7
        ffma2(acc[0][0], a0, w01); ffma2(acc[0][1], a0, w23);
        ffma2(acc[0][2], a0, w45); ffma2(acc[0][3], a0, w67);
        ffma2(acc[1][0], a1, w01); ffma2(acc[1][1], a1, w23);
        ffma2(acc[1][2], a1, w45); ffma2(acc[1][3], a1, w67);
      }
      BAR_ARRIVE_ALL(3 + (g & 1));               // xi stage g&1 empty

      if (c == NCH - 1) {
        // ---- layer2(t): reads outer(t-1) (still intact) ----
        #pragma unroll
        for (int s = 0; s < 2; ++s) {
          int o = tid + 128 * s;
          if (o < ROWS * H2) {
            int r2 = o / 10, j2 = o - r2 * 10;
            float sum = 0.f;
            #pragma unroll 5
            for (int h = 0; h < H1; ++h)
              sum = fmaf(sm.outer[r2][h], sm.W2s[h][j2], sum);
            float exc = __fadd_rn(sum, sm.b2s[j2]);
            float in2 = __fadd_rn(exc, __fmul_rn(i2[s], 0.9f));
            float o2  = __fadd_rn(in2, -1.0f);
            float pen = __fsub_rn(in2, __fmul_rn(1.5f, in2));
            i2[s] = (o2 > 0.f) ? pen : in2;
            if (t >= 19) a2[s] = __fadd_rn(a2[s], i2[s]);
          }
        }
        BAR_GEMM();   // all layer2 reads of outer(t-1) done
        // ---- LIF-1 epilogue: write outer(t), update inner1 ----
        #pragma unroll
        for (int r = 0; r < 2; ++r) {
          int row = 2 * rg + r;
          #pragma unroll
          for (int p = 0; p < 4; ++p) {
            float lo, hi;
            unpack2(acc[r][p], lo, hi);
            #pragma unroll
            for (int hh = 0; hh < 2; ++hh) {
              int j = tx * 8 + 2 * p + hh;
              if (j < H1) {
                float val = hh ? hi : lo;
                float inn = sm.inner1[row][j];
                float exc = __fadd_rn(val, sm.b1s[j]);
                float in1 = __fadd_rn(exc, __fmul_rn(inn, 0.9f));
                float o1  = fmaxf(__fadd_rn(in1, -1.0f), 0.f);
                float pen = __fsub_rn(in1, __fmul_rn(1.5f, in1));
                sm.inner1[row][j] = (o1 > 0.f) ? pen : in1;
                sm.outer[row][j]  = o1;
              }
            }
          }
        }
        ++t;
      }
      ++c; if (c == NCH) c = 0;
    }

    // ---- final layer2(98) on outer(97) ----
    BAR_GEMM();
    #pragma unroll
    for (int s = 0; s < 2; ++s) {
      int o = tid + 128 * s;
      if (o < ROWS * H2) {
        int r2 = o / 10, j2 = o - r2 * 10;
        float sum = 0.f;
        #pragma unroll 5
        for (int h = 0; h < H1; ++h)
          sum = fmaf(sm.outer[r2][h], sm.W2s[h][j2], sum);
        float exc = __fadd_rn(sum, sm.b2s[j2]);
        float in2 = __fadd_rn(exc, __fmul_rn(i2[s], 0.9f));
        float o2  = __fadd_rn(in2, -1.0f);
        float pen = __fsub_rn(in2, __fmul_rn(1.5f, in2));
        float ni  = (o2 > 0.f) ? pen : in2;
        sm.outb[r2][j2] = __fadd_rn(a2[s], ni);   // t=98 >= 19
      }
    }
  } else {
    // =================== RNG half (warps 4-10, 224 thr) ===================
    // lane->row: consecutive lanes own consecutive rows -> STS.64 lane
    // stride 8B (conflict-free).  x in thread-local (read once from gmem).
    const int rt  = tid - 128;
    const int row = rt & 15;                    // batch row 0..15
    const int m   = rt >> 4;                    // 0..13; elements kk = m+14e
    const unsigned cnt00 = (unsigned)(rA0 + row) * 784u + (unsigned)m;
    float xr[4 * NCH];                          // xr[e*14+c] = x[row, m+14e+56c]
    {
      const float* gxr = gx + (size_t)(rA0 + row) * F + m;
      #pragma unroll
      for (int e = 0; e < 4; ++e)
        for (int cc = 0; cc < NCH; ++cc)
          xr[e * NCH + cc] = gxr[14 * e + 56 * cc];
    }
    int t = 0, c = 0;
    for (int g = 0; g < NG; ++g) {
      int b = g & 1;
      if (g >= 2) BAR_SYNC_ALL(3 + b);          // xi stage b empty
      const unsigned kk0 = sm.key0[t], kk1 = sm.key1[t];
      const unsigned cbase = cnt00 + (unsigned)(c * KC);
      float2* dst = &sm.xit[b * ABUF2 + m * AROW + row];
      #pragma unroll
      for (int e = 0; e < 4; ++e) {             // element kk = m + 14e
        unsigned y0, y1;
        tf2x32(kk0, kk1, 0u, cbase + 14u * e, y0, y1);
        float v = __fmul_rn(u01(y0 ^ y1), xr[e * NCH + c]);
        dst[14 * e * AROW] = make_float2(v, v);
      }
      BAR_ARRIVE_ALL(1 + b);                    // xi stage b full
      ++c; if (c == NCH) { c = 0; ++t; }
    }
  }

  // ---- log_softmax output ------------------------------------------------
  __syncthreads();
  if (tid < ROWS) {
    float v[10], m = -3.4e38f;
    #pragma unroll
    for (int j = 0; j < 10; ++j) { v[j] = sm.outb[tid][j]; m = fmaxf(m, v[j]); }
    float s = 0.f;
    #pragma unroll
    for (int j = 0; j < 10; ++j) s = __fadd_rn(s, expf(__fsub_rn(v[j], m)));
    float l = logf(s);
    #pragma unroll
    for (int j = 0; j < 10; ++j)
      gout[(rA0 + tid) * 10 + j] = __fsub_rn(__fsub_rn(v[j], m), l);
  }
}

extern "C" void kernel_launch(void* const* d_in, const int* in_sizes, int n_in,
                              void* d_out, int out_size) {
  (void)in_sizes; (void)n_in; (void)out_size;
  const float* x  = (const float*)d_in[0];
  const float* W1 = (const float*)d_in[1];
  const float* b1 = (const float*)d_in[2];
  const float* W2 = (const float*)d_in[3];
  const float* b2 = (const float*)d_in[4];
  cudaFuncSetAttribute(snn_kernel, cudaFuncAttributeMaxDynamicSharedMemorySize,
                       (int)sizeof(Smem));
  snn_kernel<<<256, TPB, sizeof(Smem)>>>(x, W1, b1, W2, b2, (float*)d_out);
}

// round 16
// speedup vs baseline: 1.6360x; 1.6360x over previous
#include <cuda_runtime.h>
#include <cstdint>

// ---------------------------------------------------------------------------
// SpikingNet, JAX threefry PARTITIONABLE mode (confirmed R4).
// R16 = R12 (best, 4916us, race-free) with KC doubled: 56 -> 112 (NCH 7).
// Halves barrier/staging events (686 rendezvous total), doubles FFMA stretch.
// 128 CTAs x 576 thr: warps 0-3 GEMM (4 rows x 8 cols/thread, FFMA2),
// warps 4-17 threefry RNG (8 evals/chunk, lane->row conflict-free stores,
// x in thread-local).  2-deep xi ring, named barriers
// (FULL[b]=1+b, EMPTY[b]=3+b, GEMM-internal=5), stage_w AFTER sync.
// Per-output arithmetic identical to R4-R15 (ascending-k FMA chains).
// ---------------------------------------------------------------------------

namespace {
constexpr int F     = 784;
constexpr int KC    = 112;                // K-chunk (doubled vs R12)
constexpr int NCH   = 7;                  // 784/112
constexpr int H1    = 100;
constexpr int H2    = 10;
constexpr int WROW  = 140;                // swizzled W row pitch (words)
constexpr int WBUFW = KC * WROW;          // 15680 floats per W buffer
constexpr int AROW  = 34;                 // xit row pitch (float2)
constexpr int ABUF2 = KC * AROW;          // 3808 float2 per xi stage
constexpr int NSTEP = 98;                 // layer1 steps
constexpr int NG    = NSTEP * NCH;        // 686 chunks
constexpr int TPB   = 576;

struct Smem {
  float    W[2 * WBUFW];          // 125,440 B (swizzled, dbl buffer)
  float2   xit[2 * ABUF2];        //  60,928 B ({v,v} dup, [stage][k][row])
  float    outer[32][H1];         //  12,800 B
  float    inner1[32][H1];        //  12,800 B
  float    W2s[H1][H2];           //   4,000 B
  float    b1s[H1];
  float    b2s[H2];
  float    outb[32][H2];
  unsigned key0[NSTEP], key1[NSTEP];
};                                 // ~213.4 KB (< 227 KB cap)

// W col-group swizzle (R6-proven, injective): group g (8 cols) at word
// (g/4)*36 + (g%4)*8, pitch 140.
__device__ __forceinline__ int woff(int g) { return (g >> 2) * 36 + (g & 3) * 8; }

__device__ __forceinline__ void tf2x32(unsigned k0, unsigned k1,
                                       unsigned x0, unsigned x1,
                                       unsigned& y0, unsigned& y1) {
  unsigned k2 = k0 ^ k1 ^ 0x1BD11BDAu;
#define TFR(r) { x0 += x1; x1 = __funnelshift_l(x1, x1, (r)); x1 ^= x0; }
  x0 += k0; x1 += k1;
  TFR(13) TFR(15) TFR(26) TFR(6)
  x0 += k1; x1 += k2 + 1u;
  TFR(17) TFR(29) TFR(16) TFR(24)
  x0 += k2; x1 += k0 + 2u;
  TFR(13) TFR(15) TFR(26) TFR(6)
  x0 += k0; x1 += k1 + 3u;
  TFR(17) TFR(29) TFR(16) TFR(24)
  x0 += k1; x1 += k2 + 4u;
  TFR(13) TFR(15) TFR(26) TFR(6)
  x0 += k2; x1 += k0 + 5u;
#undef TFR
  y0 = x0; y1 = x1;
}

__device__ __forceinline__ float u01(unsigned bits) {
  return __fadd_rn(__uint_as_float((bits >> 9) | 0x3F800000u), -1.0f);
}

__device__ __forceinline__ void ffma2(unsigned long long& d,
                                      unsigned long long a,
                                      unsigned long long b) {
  asm("fma.rn.f32x2 %0, %1, %2, %0;" : "+l"(d) : "l"(a), "l"(b));
}

__device__ __forceinline__ void lds2u64(unsigned long long& a,
                                        unsigned long long& b, unsigned addr) {
  asm volatile("ld.shared.v2.u64 {%0,%1}, [%2];" : "=l"(a), "=l"(b) : "r"(addr));
}

__device__ __forceinline__ void unpack2(unsigned long long v, float& lo, float& hi) {
  asm("mov.b64 {%0,%1}, %2;" : "=f"(lo), "=f"(hi) : "l"(v));
}

// FULL[b] = 1+b, EMPTY[b] = 3+b (b=0,1), GEMM-internal = 5
#define BAR_SYNC_ALL(id)   asm volatile("bar.sync %0, 576;"   :: "r"(id) : "memory")
#define BAR_ARRIVE_ALL(id) asm volatile("bar.arrive %0, 576;" :: "r"(id) : "memory")
#define BAR_GEMM()         asm volatile("bar.sync 5, 128;" ::: "memory")

// stage W chunk (swizzled) via cp.async; GEMM threads only (stride 128)
__device__ __forceinline__ void stage_w(const float* __restrict__ gW1,
                                        Smem& sm, int chunk, int buf, int tid) {
  const float* src0 = gW1 + chunk * KC * H1;
  float* dst0 = &sm.W[buf * WBUFW];
  for (int seg = tid; seg < KC * 25; seg += 128) {
    int row = seg / 25, p = seg - row * 25;       // p: 16B piece (4 cols)
    int dw = row * WROW + woff(p >> 1) + (p & 1) * 4;
    unsigned d = (unsigned)__cvta_generic_to_shared(dst0 + dw);
    const float* s = src0 + row * H1 + p * 4;
    asm volatile("cp.async.ca.shared.global [%0], [%1], 16;\n" :: "r"(d), "l"(s));
  }
}
}  // namespace

__global__ void __launch_bounds__(TPB, 1)
snn_kernel(const float* __restrict__ gx, const float* __restrict__ gW1,
           const float* __restrict__ gb1, const float* __restrict__ gW2,
           const float* __restrict__ gb2, float* __restrict__ gout) {
  extern __shared__ char smraw[];
  Smem& sm = *reinterpret_cast<Smem*>(smraw);
  const int tid = threadIdx.x;
  const int rA0 = blockIdx.x * 32;

  // ---- init --------------------------------------------------------------
  for (int e = tid; e < 2 * WBUFW; e += TPB) sm.W[e] = 0.f;   // pad cols stay 0
  for (int e = tid; e < 32 * H1; e += TPB) {
    (&sm.outer[0][0])[e]  = 0.f;
    (&sm.inner1[0][0])[e] = 0.f;
  }
  for (int e = tid; e < H1 * H2; e += TPB) (&sm.W2s[0][0])[e] = gW2[e];
  if (tid < H1) sm.b1s[tid] = gb1[tid];
  if (tid < H2) sm.b2s[tid] = gb2[tid];
  if (tid < NSTEP) {   // foldlike split: keys[t] = threefry((0,42),(0,t))
    unsigned a0, a1;
    tf2x32(0u, 42u, 0u, (unsigned)tid, a0, a1);
    sm.key0[tid] = a0; sm.key1[tid] = a1;
  }
  __syncthreads();

  if (tid < 128) {
    // =================== GEMM / layer2 half (warps 0-3) ===================
    const int tx = tid & 15;           // col group: cols tx*8 .. tx*8+7
    const int rg = tid >> 4;           // row group: rows 4rg .. 4rg+3
    const unsigned wb0 = (unsigned)__cvta_generic_to_shared(&sm.W[0]) +
                         (unsigned)(woff(tx) * 4);
    const unsigned ab0 = (unsigned)__cvta_generic_to_shared(&sm.xit[0]) +
                         (unsigned)(rg * 32);        // rows 4rg..: byte 32*rg
    // layer2 outputs: o = tid + 128*s (s<3), valid o<320; r=o/10, j=o%10
    float i2[3] = {0.f, 0.f, 0.f}, a2[3] = {0.f, 0.f, 0.f};

    stage_w(gW1, sm, 0, 0, tid);                 // prologue: chunk 0 -> buf 0
    asm volatile("cp.async.commit_group;\n");

    unsigned long long acc[4][4];
    int t = 0, c = 0;
    for (int g = 0; g < NG; ++g) {
      if (c == 0) {
        #pragma unroll
        for (int r = 0; r < 4; ++r)
          #pragma unroll
          for (int p = 0; p < 4; ++p) acc[r][p] = 0ull;
      }
      BAR_SYNC_ALL(1 + (g & 1));                 // xi stage g&1 full; all GEMM
                                                 // peers past chunk g-1 FFMA
      int nc = (c + 1 == NCH) ? 0 : c + 1;       // stage W AFTER rendezvous
      stage_w(gW1, sm, nc, (g + 1) & 1, tid);    // (race-free, R12-proven)
      asm volatile("cp.async.commit_group;\n");
      asm volatile("cp.async.wait_group 1;\n");  // W[g&1] ready

      const unsigned wB = wb0 + (unsigned)((g & 1) * (WBUFW * 4));
      const unsigned aB = ab0 + (unsigned)((g & 1) * (ABUF2 * 8));
      #pragma unroll 8
      for (int k = 0; k < KC; ++k) {
        unsigned long long a0, a1, a2v, a3, w01, w23, w45, w67;
        lds2u64(a0, a1,   aB + (unsigned)k * 272u);        // rows 4rg,4rg+1
        lds2u64(a2v, a3,  aB + (unsigned)k * 272u + 16u);  // rows 4rg+2,4rg+3
        lds2u64(w01, w23, wB + (unsigned)k * 560u);        // cols tx*8..+3
        lds2u64(w45, w67, wB + (unsigned)k * 560u + 16u);  // cols tx*8+4..+7
        ffma2(acc[0][0], a0, w01);  ffma2(acc[0][1], a0, w23);
        ffma2(acc[0][2], a0, w45);  ffma2(acc[0][3], a0, w67);
        ffma2(acc[1][0], a1, w01);  ffma2(acc[1][1], a1, w23);
        ffma2(acc[1][2], a1, w45);  ffma2(acc[1][3], a1, w67);
        ffma2(acc[2][0], a2v, w01); ffma2(acc[2][1], a2v, w23);
        ffma2(acc[2][2], a2v, w45); ffma2(acc[2][3], a2v, w67);
        ffma2(acc[3][0], a3, w01);  ffma2(acc[3][1], a3, w23);
        ffma2(acc[3][2], a3, w45);  ffma2(acc[3][3], a3, w67);
      }
      BAR_ARRIVE_ALL(3 + (g & 1));               // xi stage g&1 empty

      if (c == NCH - 1) {
        // ---- layer2(t): reads outer(t-1) (still intact) ----
        #pragma unroll
        for (int s = 0; s < 3; ++s) {
          int o = tid + 128 * s;
          if (o < 320) {
            int r2 = o / 10, j2 = o - r2 * 10;
            float sum = 0.f;
            #pragma unroll 5
            for (int h = 0; h < H1; ++h)
              sum = fmaf(sm.outer[r2][h], sm.W2s[h][j2], sum);
            float exc = __fadd_rn(sum, sm.b2s[j2]);
            float in2 = __fadd_rn(exc, __fmul_rn(i2[s], 0.9f));
            float o2  = __fadd_rn(in2, -1.0f);
            float pen = __fsub_rn(in2, __fmul_rn(1.5f, in2));
            i2[s] = (o2 > 0.f) ? pen : in2;
            if (t >= 19) a2[s] = __fadd_rn(a2[s], i2[s]);
          }
        }
        BAR_GEMM();   // all layer2 reads of outer(t-1) done
        // ---- LIF-1 epilogue: write outer(t), update inner1 ----
        #pragma unroll
        for (int r = 0; r < 4; ++r) {
          int row = 4 * rg + r;
          #pragma unroll
          for (int p = 0; p < 4; ++p) {
            float lo, hi;
            unpack2(acc[r][p], lo, hi);
            #pragma unroll
            for (int hh = 0; hh < 2; ++hh) {
              int j = tx * 8 + 2 * p + hh;
              if (j < H1) {
                float val = hh ? hi : lo;
                float inn = sm.inner1[row][j];
                float exc = __fadd_rn(val, sm.b1s[j]);
                float in1 = __fadd_rn(exc, __fmul_rn(inn, 0.9f));
                float o1  = fmaxf(__fadd_rn(in1, -1.0f), 0.f);
                float pen = __fsub_rn(in1, __fmul_rn(1.5f, in1));
                sm.inner1[row][j] = (o1 > 0.f) ? pen : in1;
                sm.outer[row][j]  = o1;
              }
            }
          }
        }
        ++t;
      }
      ++c; if (c == NCH) c = 0;
    }

    // ---- final layer2(98) on outer(97) ----
    BAR_GEMM();
    #pragma unroll
    for (int s = 0; s < 3; ++s) {
      int o = tid + 128 * s;
      if (o < 320) {
        int r2 = o / 10, j2 = o - r2 * 10;
        float sum = 0.f;
        #pragma unroll 5
        for (int h = 0; h < H1; ++h)
          sum = fmaf(sm.outer[r2][h], sm.W2s[h][j2], sum);
        float exc = __fadd_rn(sum, sm.b2s[j2]);
        float in2 = __fadd_rn(exc, __fmul_rn(i2[s], 0.9f));
        float o2  = __fadd_rn(in2, -1.0f);
        float pen = __fsub_rn(in2, __fmul_rn(1.5f, in2));
        float ni  = (o2 > 0.f) ? pen : in2;
        sm.outb[r2][j2] = __fadd_rn(a2[s], ni);   // t=98 >= 19
      }
    }
  } else {
    // =================== RNG half (warps 4-17, 448 thr) ===================
    // lane->row mapping: consecutive lanes own consecutive rows -> STS.64
    // lane stride 8B (conflict-free).  x in thread-local (read once, gmem).
    // Per chunk: 8 evals, elements kk = m + 14e (e<8) of the 112-wide chunk.
    const int rt  = tid - 128;
    const int row = rt & 31;
    const int m   = rt >> 5;                    // 0..13
    const unsigned cnt00 = (unsigned)(rA0 + row) * 784u + (unsigned)m;
    float xr[8 * NCH];                          // xr[e*7+c] = x[row, m+14e+112c]
    {
      const float* gxr = gx + (size_t)(rA0 + row) * F + m;
      #pragma unroll
      for (int e = 0; e < 8; ++e)
        for (int cc = 0; cc < NCH; ++cc)
          xr[e * NCH + cc] = gxr[14 * e + 112 * cc];
    }
    int t = 0, c = 0;
    for (int g = 0; g < NG; ++g) {
      int b = g & 1;
      if (g >= 2) BAR_SYNC_ALL(3 + b);          // xi stage b empty
      const unsigned kk0 = sm.key0[t], kk1 = sm.key1[t];
      const unsigned cbase = cnt00 + (unsigned)(c * KC);
      float2* dst = &sm.xit[b * ABUF2 + m * AROW + row];
      #pragma unroll
      for (int e = 0; e < 8; ++e) {             // element kk = m + 14e
        unsigned y0, y1;
        tf2x32(kk0, kk1, 0u, cbase + 14u * e, y0, y1);
        float v = __fmul_rn(u01(y0 ^ y1), xr[e * NCH + c]);
        dst[14 * e * AROW] = make_float2(v, v);
      }
      BAR_ARRIVE_ALL(1 + b);                    // xi stage b full
      ++c; if (c == NCH) { c = 0; ++t; }
    }
  }

  // ---- log_softmax output ------------------------------------------------
  __syncthreads();
  if (tid < 32) {
    float v[10], m = -3.4e38f;
    #pragma unroll
    for (int j = 0; j < 10; ++j) { v[j] = sm.outb[tid][j]; m = fmaxf(m, v[j]); }
    float s = 0.f;
    #pragma unroll
    for (int j = 0; j < 10; ++j) s = __fadd_rn(s, expf(__fsub_rn(v[j], m)));
    float l = logf(s);
    #pragma unroll
    for (int j = 0; j < 10; ++j)
      gout[(rA0 + tid) * 10 + j] = __fsub_rn(__fsub_rn(v[j], m), l);
  }
}

extern "C" void kernel_launch(void* const* d_in, const int* in_sizes, int n_in,
                              void* d_out, int out_size) {
  (void)in_sizes; (void)n_in; (void)out_size;
  const float* x  = (const float*)d_in[0];
  const float* W1 = (const float*)d_in[1];
  const float* b1 = (const float*)d_in[2];
  const float* W2 = (const float*)d_in[3];
  const float* b2 = (const float*)d_in[4];
  cudaFuncSetAttribute(snn_kernel, cudaFuncAttributeMaxDynamicSharedMemorySize,
                       (int)sizeof(Smem));
  snn_kernel<<<128, TPB, sizeof(Smem)>>>(x, W1, b1, W2, b2, (float*)d_out);
}